// round 6
// baseline (speedup 1.0000x reference)
#include <cuda_runtime.h>
#include <math.h>
#include <stdint.h>

#define TMH    199
#define BBATCH 32
#define TTOT   200
#define DIM    100
#define NROOT  (BBATCH*TMH)   /* 6368 */
#define RKK    10
#define NUMS   1200
#define T2ROWS (NUMS*4)       /* 4800 */

/* ------------------------------------------------------------------ */
/* scratch                                                             */
/* ------------------------------------------------------------------ */
__device__ __align__(16) float g_plain[NROOT*DIM];
__device__ __align__(16) float g_Qe   [NROOT*DIM];
__device__ __align__(16) float g_embq [NROOT*DIM];
__device__ __align__(16) float g_t2   [T2ROWS*DIM];
__device__ __align__(16) float g_t1a  [NUMS*DIM];
__device__ __align__(16) float g_t1b  [NUMS*DIM];
__device__ __align__(16) float g_e0y  [NROOT*DIM];
__device__ __align__(16) float g_lstm [NROOT*DIM];
__device__ __align__(16) float g_sc   [NROOT*200];
__device__ __align__(16) float g_zero [DIM];      /* stays 0 */
__device__ float g_akl[NROOT];
__device__ float g_aqe[NROOT];
__device__ float g_ast[NUMS];
__device__ float g_akzero;
__device__ float g_aqzero;
__device__ int   g_topk[NROOT*RKK];
__device__ int   g_active[NROOT];
__device__ int   g_activeq[NROOT];
__device__ int   g_cnt;

/* gather modes */
#define GM_PLAIN 0
#define GM_T2X   1
#define GM_T1X   2
#define GM_T1B   3
#define GM_E00   4
#define GM_E01   5
#define GM_E02   6
/* output buffers */
#define OB_T2   0
#define OB_T1A  1
#define OB_T1B  2
#define OB_E0Y  3
#define OB_EMBQ 4   /* scatter via g_active */

__device__ __forceinline__ float warp_sum(float v) {
#pragma unroll
    for (int o = 16; o; o >>= 1) v += __shfl_xor_sync(0xffffffffu, v, o);
    return v;
}
/* fast tanh: 1 - 2/(e^{2x}+1); exact +-1 saturation at |x| large */
__device__ __forceinline__ float fast_tanh(float x) {
    return 1.f - __fdividef(2.f, __expf(2.f*x) + 1.f);
}
__device__ __forceinline__ float fast_sigm(float x) {
    return __fdividef(1.f, 1.f + __expf(-x));
}

/* ------------------------------------------------------------------ */
__global__ void k_init(float* out, const float* __restrict__ bq,
                       const float* __restrict__ bk,
                       const float* __restrict__ watt) {
    int tid = threadIdx.x, w = tid >> 5, lane = tid & 31;
    if (tid < BBATCH) out[tid*TTOT] = 0.5f;
    if (tid == 64)    g_cnt = 0;
    if (w == 0) {
        float s = 0.f;
        for (int c = lane; c < DIM; c += 32) s += fast_tanh(bq[c]) * watt[DIM + c];
        s = warp_sum(s);
        if (lane == 0) g_akzero = s;
    } else if (w == 1) {
        float s = 0.f;
        for (int c = lane; c < DIM; c += 32) s += fast_tanh(bk[c]) * watt[c];
        s = warp_sum(s);
        if (lane == 0) g_aqzero = s;
    }
}

/* ------------------------------------------------------------------ */
__global__ void k_prep(const int* __restrict__ question,
                       const int* __restrict__ mask,
                       const float* __restrict__ emb_q) {
    int w = threadIdx.x >> 5, lane = threadIdx.x & 31;
    int root = blockIdx.x*4 + w;
    if (root >= NROOT) return;
    int b = root / TMH, t = root % TMH;
    int qh = question[b*TTOT + t];
    int qn = question[b*TTOT + t + 1];
    if (lane < 25) {
        const float4* eq = (const float4*)emb_q;
        float4 vh = eq[qh*25 + lane];
        float4 vn = eq[qn*25 + lane];
        ((float4*)g_plain)[root*25 + lane] = vh;
        ((float4*)g_embq )[root*25 + lane] = vh;
        ((float4*)g_Qe   )[root*25 + lane] = vn;
    }
    if (lane == 0 && mask[b*TTOT + t] == 1) {
        int pos = atomicAdd(&g_cnt, 1);
        g_active[pos]  = root;
        g_activeq[pos] = qh;
    }
}

/* ------------------------------------------------------------------ */
/* fused gather + tile GEMM : Y[r] = tanh( x(r) @ W(100,100)^T + b )   */
/* x(r) = p0[.] + 0.25*(pn0[.]+pn1[.]+pn2[.]+pn3[.])                   */
/* ------------------------------------------------------------------ */
__global__ void k_gemmg(int gmode, int oid,
                        const float* __restrict__ W, const float* __restrict__ bias,
                        int rows, int use_cnt,
                        const int* __restrict__ qnb, const int* __restrict__ snb,
                        const float* __restrict__ emb_q, const float* __restrict__ emb_s) {
    __shared__ __align__(16) float Xs[16][100];
    __shared__ float Ws[100][101];
    __shared__ const float* s_p0[16];
    __shared__ const float* s_pn[16][4];
    if (use_cnt) rows = g_cnt;
    int r0 = blockIdx.x * 16;
    if (r0 >= rows) return;
    int tid = threadIdx.x;
    int tx = tid & 31, ty = tid >> 5;

    if (tid < 16) {
        int gr = r0 + tid;
        const float *p0 = g_zero, *a0 = g_zero, *a1 = g_zero, *a2 = g_zero, *a3 = g_zero;
        if (gr < rows) {
            switch (gmode) {
            case GM_PLAIN:
                p0 = g_e0y + (size_t)gr*DIM;
                break;
            case GM_T2X: {
                int n2 = snb[gr];
                p0 = emb_q + (size_t)n2*DIM;
                a0 = emb_s + (size_t)qnb[n2*4 + 0]*DIM;
                a1 = emb_s + (size_t)qnb[n2*4 + 1]*DIM;
                a2 = emb_s + (size_t)qnb[n2*4 + 2]*DIM;
                a3 = emb_s + (size_t)qnb[n2*4 + 3]*DIM;
            } break;
            case GM_T1X: {
                p0 = emb_s + (size_t)gr*DIM;
                a0 = emb_q + (size_t)snb[gr*4 + 0]*DIM;
                a1 = emb_q + (size_t)snb[gr*4 + 1]*DIM;
                a2 = emb_q + (size_t)snb[gr*4 + 2]*DIM;
                a3 = emb_q + (size_t)snb[gr*4 + 3]*DIM;
            } break;
            case GM_T1B: {
                p0 = g_t1a + (size_t)gr*DIM;
                a0 = g_t2 + (size_t)(gr*4 + 0)*DIM;
                a1 = g_t2 + (size_t)(gr*4 + 1)*DIM;
                a2 = g_t2 + (size_t)(gr*4 + 2)*DIM;
                a3 = g_t2 + (size_t)(gr*4 + 3)*DIM;
            } break;
            case GM_E00: {
                int q = g_activeq[gr];
                p0 = emb_q + (size_t)q*DIM;
                a0 = emb_s + (size_t)qnb[q*4 + 0]*DIM;
                a1 = emb_s + (size_t)qnb[q*4 + 1]*DIM;
                a2 = emb_s + (size_t)qnb[q*4 + 2]*DIM;
                a3 = emb_s + (size_t)qnb[q*4 + 3]*DIM;
            } break;
            case GM_E01: {
                int q = g_activeq[gr];
                p0 = g_e0y + (size_t)gr*DIM;
                a0 = g_t1a + (size_t)qnb[q*4 + 0]*DIM;
                a1 = g_t1a + (size_t)qnb[q*4 + 1]*DIM;
                a2 = g_t1a + (size_t)qnb[q*4 + 2]*DIM;
                a3 = g_t1a + (size_t)qnb[q*4 + 3]*DIM;
            } break;
            default: { /* GM_E02 */
                int q = g_activeq[gr];
                p0 = g_e0y + (size_t)gr*DIM;
                a0 = g_t1b + (size_t)qnb[q*4 + 0]*DIM;
                a1 = g_t1b + (size_t)qnb[q*4 + 1]*DIM;
                a2 = g_t1b + (size_t)qnb[q*4 + 2]*DIM;
                a3 = g_t1b + (size_t)qnb[q*4 + 3]*DIM;
            } break;
            }
        }
        s_p0[tid] = p0;
        s_pn[tid][0] = a0; s_pn[tid][1] = a1; s_pn[tid][2] = a2; s_pn[tid][3] = a3;
    }
    for (int idx = tid; idx < 100*100; idx += 128) {
        int c = idx / 100, j = idx % 100;
        Ws[c][j] = W[(size_t)c*100 + j];
    }
    __syncthreads();
    /* vectorized gather: 16 rows x 25 float4 */
    for (int idx = tid; idx < 16*25; idx += 128) {
        int r = idx / 25, j = idx % 25;
        float4 v  = ((const float4*)s_p0[r])[j];
        float4 n0 = ((const float4*)s_pn[r][0])[j];
        float4 n1 = ((const float4*)s_pn[r][1])[j];
        float4 n2 = ((const float4*)s_pn[r][2])[j];
        float4 n3 = ((const float4*)s_pn[r][3])[j];
        v.x += 0.25f*(n0.x + n1.x + n2.x + n3.x);
        v.y += 0.25f*(n0.y + n1.y + n2.y + n3.y);
        v.z += 0.25f*(n0.z + n1.z + n2.z + n3.z);
        v.w += 0.25f*(n0.w + n1.w + n2.w + n3.w);
        ((float4*)&Xs[r][0])[j] = v;
    }
    __syncthreads();

    float acc[4][4];
#pragma unroll
    for (int i = 0; i < 4; i++)
#pragma unroll
        for (int c = 0; c < 4; c++) acc[i][c] = 0.f;
    bool w3ok = (tx < 4);
#pragma unroll 2
    for (int j4 = 0; j4 < 100; j4 += 4) {
        float xr[4][4];
#pragma unroll
        for (int i = 0; i < 4; i++)
            *(float4*)xr[i] = *(const float4*)&Xs[ty*4 + i][j4];
#pragma unroll
        for (int jj = 0; jj < 4; jj++) {
            int j = j4 + jj;
            float wv[4];
            wv[0] = Ws[tx][j];
            wv[1] = Ws[tx + 32][j];
            wv[2] = Ws[tx + 64][j];
            wv[3] = w3ok ? Ws[tx + 96][j] : 0.f;
#pragma unroll
            for (int i = 0; i < 4; i++)
#pragma unroll
                for (int c = 0; c < 4; c++) acc[i][c] += xr[i][jj]*wv[c];
        }
    }

    float* Y = (oid == OB_T2)  ? g_t2
             : (oid == OB_T1A) ? g_t1a
             : (oid == OB_T1B) ? g_t1b
             : (oid == OB_E0Y) ? g_e0y : g_embq;
#pragma unroll
    for (int i = 0; i < 4; i++) {
        int r = r0 + ty*4 + i;
        if (r >= rows) continue;
        size_t orow = (oid == OB_EMBQ) ? (size_t)g_active[r] : (size_t)r;
#pragma unroll
        for (int cc = 0; cc < 4; cc++) {
            int c = tx + cc*32;
            if (c < 100)
                Y[orow*100 + c] = fast_tanh(acc[i][cc] + bias[c]);
        }
    }
}

/* ------------------------------------------------------------------ */
/* fused LSTM: x=[embq | emb_r[resp]], 3 gate GEMMs, combine           */
/* ------------------------------------------------------------------ */
__global__ void k_lstm(const int* __restrict__ response,
                       const float* __restrict__ emb_r,
                       const float* __restrict__ Wih,
                       const float* __restrict__ lb) {
    __shared__ __align__(16) float Xs[16][100];
    __shared__ float Ws[100][101];
    int r0 = blockIdx.x * 16;
    int tid = threadIdx.x;
    int tx = tid & 31, ty = tid >> 5;
    float acc[3][4][4];
#pragma unroll
    for (int s = 0; s < 3; s++)
#pragma unroll
        for (int i = 0; i < 4; i++)
#pragma unroll
            for (int c = 0; c < 4; c++) acc[s][i][c] = 0.f;
    const int slab_row[3] = {0, 200, 300};   /* i, g, o */
    bool w3ok = (tx < 4);

    for (int kt = 0; kt < 200; kt += 100) {
        __syncthreads();
        for (int idx = tid; idx < 16*25; idx += 128) {
            int r = idx / 25, j = idx % 25;
            int gr = r0 + r;
            float4 v = make_float4(0.f,0.f,0.f,0.f);
            if (gr < NROOT) {
                if (kt == 0) v = ((const float4*)g_embq)[(size_t)gr*25 + j];
                else {
                    int b = gr / TMH, t = gr % TMH;
                    v = ((const float4*)emb_r)[(size_t)response[b*TTOT + t]*25 + j];
                }
            }
            ((float4*)&Xs[r][0])[j] = v;
        }
#pragma unroll
        for (int s = 0; s < 3; s++) {
            __syncthreads();
            for (int idx = tid; idx < 100*100; idx += 128) {
                int c = idx / 100, j = idx % 100;
                Ws[c][j] = Wih[(size_t)(slab_row[s] + c)*200 + kt + j];
            }
            __syncthreads();
#pragma unroll 2
            for (int j4 = 0; j4 < 100; j4 += 4) {
                float xr[4][4];
#pragma unroll
                for (int i = 0; i < 4; i++)
                    *(float4*)xr[i] = *(const float4*)&Xs[ty*4 + i][j4];
#pragma unroll
                for (int jj = 0; jj < 4; jj++) {
                    int j = j4 + jj;
                    float wv[4];
                    wv[0] = Ws[tx][j];
                    wv[1] = Ws[tx + 32][j];
                    wv[2] = Ws[tx + 64][j];
                    wv[3] = w3ok ? Ws[tx + 96][j] : 0.f;
#pragma unroll
                    for (int i = 0; i < 4; i++)
#pragma unroll
                        for (int c = 0; c < 4; c++) acc[s][i][c] += xr[i][jj]*wv[c];
                }
            }
        }
    }
#pragma unroll
    for (int i = 0; i < 4; i++) {
        int r = r0 + ty*4 + i;
        if (r >= NROOT) continue;
#pragma unroll
        for (int cc = 0; cc < 4; cc++) {
            int c = tx + cc*32;
            if (c >= 100) continue;
            float gi = acc[0][i][cc] + lb[c];
            float gg = acc[1][i][cc] + lb[200 + c];
            float go = acc[2][i][cc] + lb[300 + c];
            g_lstm[(size_t)r*100 + c] = fast_sigm(go) * fast_tanh(fast_sigm(gi) * fast_tanh(gg));
        }
    }
}

/* ------------------------------------------------------------------ */
/* merged scalar GEMV tables                                           */
/* ------------------------------------------------------------------ */
__global__ void k_gemvs3(const float* __restrict__ Wq, const float* __restrict__ bq,
                         const float* __restrict__ Wk, const float* __restrict__ bk,
                         const float* __restrict__ watt,
                         const float* __restrict__ emb_s) {
    __shared__ __align__(16) float Xs[16][100];
    __shared__ float Ws[100][101];
    int blk = blockIdx.x;
    const float *X, *W, *bias, *wvec;
    float* O;
    int rows, r0;
    if (blk < 398)      { X = g_lstm; W = Wq; bias = bq; wvec = watt + DIM; O = g_akl; rows = NROOT; r0 = blk*16; }
    else if (blk < 796) { X = g_Qe;   W = Wk; bias = bk; wvec = watt;       O = g_aqe; rows = NROOT; r0 = (blk-398)*16; }
    else                { X = emb_s;  W = Wk; bias = bk; wvec = watt;       O = g_ast; rows = NUMS;  r0 = (blk-796)*16; }
    if (r0 >= rows) return;
    int tid = threadIdx.x;
    int tx = tid & 31, ty = tid >> 5;
    float acc[4][4];
#pragma unroll
    for (int i = 0; i < 4; i++)
#pragma unroll
        for (int c = 0; c < 4; c++) acc[i][c] = 0.f;
    for (int idx = tid; idx < 16*100; idx += 128) {
        int r = idx / 100, j = idx % 100;
        int gr = r0 + r;
        Xs[r][j] = (gr < rows) ? X[(size_t)gr*100 + j] : 0.f;
    }
    for (int idx = tid; idx < 100*100; idx += 128) {
        int c = idx / 100, j = idx % 100;
        Ws[c][j] = W[(size_t)c*100 + j];
    }
    __syncthreads();
    bool w3ok = (tx < 4);
#pragma unroll 2
    for (int j4 = 0; j4 < 100; j4 += 4) {
        float xr[4][4];
#pragma unroll
        for (int i = 0; i < 4; i++)
            *(float4*)xr[i] = *(const float4*)&Xs[ty*4 + i][j4];
#pragma unroll
        for (int jj = 0; jj < 4; jj++) {
            int j = j4 + jj;
            float wv[4];
            wv[0] = Ws[tx][j];
            wv[1] = Ws[tx + 32][j];
            wv[2] = Ws[tx + 64][j];
            wv[3] = w3ok ? Ws[tx + 96][j] : 0.f;
#pragma unroll
            for (int i = 0; i < 4; i++)
#pragma unroll
                for (int c = 0; c < 4; c++) acc[i][c] += xr[i][jj]*wv[c];
        }
    }
    float bv[4], wvv[4];
#pragma unroll
    for (int cc = 0; cc < 4; cc++) {
        int c = tx + cc*32;
        bv[cc]  = (c < 100) ? bias[c] : 0.f;
        wvv[cc] = (c < 100) ? wvec[c] : 0.f;
    }
#pragma unroll
    for (int i = 0; i < 4; i++) {
        float s = 0.f;
#pragma unroll
        for (int cc = 0; cc < 4; cc++) {
            int c = tx + cc*32;
            if (c < 100) s += fast_tanh(acc[i][cc] + bv[cc]) * wvv[cc];
        }
        s = warp_sum(s);
        int r = r0 + ty*4 + i;
        if (tx == 0 && r < rows) O[r] = s;
    }
}

/* ------------------------------------------------------------------ */
/* scores GEMM : g_sc[root][s] = Qe[root] . plain[b][s]                */
/* ------------------------------------------------------------------ */
__global__ void k_sgemm() {
    __shared__ __align__(16) float Xs[16][100];
    __shared__ float Ps[100][101];
    int t0 = blockIdx.x * 16;
    int s0 = blockIdx.y * 100;
    int b  = blockIdx.z;
    if (s0 > t0 + 14) return;
    int tid = threadIdx.x;
    int tx = tid & 31, ty = tid >> 5;
    for (int idx = tid; idx < 16*100; idx += 128) {
        int r = idx / 100, j = idx % 100;
        int t = t0 + r;
        Xs[r][j] = (t < TMH) ? g_Qe[(size_t)(b*TMH + t)*100 + j] : 0.f;
    }
    for (int idx = tid; idx < 100*100; idx += 128) {
        int s = idx / 100, d = idx % 100;
        int gs = s0 + s;
        Ps[s][d] = (gs < TMH) ? g_plain[(size_t)(b*TMH + gs)*100 + d] : 0.f;
    }
    __syncthreads();
    float acc[4][4];
#pragma unroll
    for (int i = 0; i < 4; i++)
#pragma unroll
        for (int c = 0; c < 4; c++) acc[i][c] = 0.f;
    bool w3ok = (tx < 4);
#pragma unroll 2
    for (int j4 = 0; j4 < 100; j4 += 4) {
        float xr[4][4];
#pragma unroll
        for (int i = 0; i < 4; i++)
            *(float4*)xr[i] = *(const float4*)&Xs[ty*4 + i][j4];
#pragma unroll
        for (int jj = 0; jj < 4; jj++) {
            int j = j4 + jj;
            float wv[4];
            wv[0] = Ps[tx][j];
            wv[1] = Ps[tx + 32][j];
            wv[2] = Ps[tx + 64][j];
            wv[3] = w3ok ? Ps[tx + 96][j] : 0.f;
#pragma unroll
            for (int i = 0; i < 4; i++)
#pragma unroll
                for (int c = 0; c < 4; c++) acc[i][c] += xr[i][jj]*wv[c];
        }
    }
#pragma unroll
    for (int i = 0; i < 4; i++) {
        int t = t0 + ty*4 + i;
        if (t >= TMH) continue;
#pragma unroll
        for (int cc = 0; cc < 4; cc++) {
            int c = tx + cc*32;
            int s = s0 + c;
            if (c < 100 && s < TMH)
                g_sc[(size_t)(b*TMH + t)*200 + s] = acc[i][cc];
        }
    }
}

/* ------------------------------------------------------------------ */
/* stable top-10 (tie: value desc, index asc)                          */
/* ------------------------------------------------------------------ */
__global__ void k_topk() {
    int w = threadIdx.x >> 5, lane = threadIdx.x & 31;
    int root = blockIdx.x*4 + w;
    if (root >= NROOT) return;
    int t = root % TMH;
    float rv[7];
#pragma unroll
    for (int u = 0; u < 7; u++) {
        int s = lane + u*32;
        rv[u] = (s < t) ? g_sc[(size_t)root*200 + s] : -3.4e38f;
    }
#pragma unroll
    for (int r = 0; r < RKK; r++) {
        float bv = -3.4e38f;
        int   bi = 0x7fffffff;
#pragma unroll
        for (int u = 0; u < 7; u++) {
            int s = lane + u*32;
            if (s < t && rv[u] > bv) { bv = rv[u]; bi = s; }
        }
#pragma unroll
        for (int o = 16; o; o >>= 1) {
            float ov = __shfl_xor_sync(0xffffffffu, bv, o);
            int   oi = __shfl_xor_sync(0xffffffffu, bi, o);
            if (ov > bv || (ov == bv && oi < bi)) { bv = ov; bi = oi; }
        }
        if (lane == 0)
            g_topk[root*RKK + r] = (bv > -1e29f) ? bi : -1;
        if (bi != 0x7fffffff && (bi & 31) == lane)
            rv[bi >> 5] = -3.4e38f;
    }
}

/* ------------------------------------------------------------------ */
/* final attention (+ state rows for t==TMH-1)                         */
/* ------------------------------------------------------------------ */
__global__ void k_att(const int* __restrict__ question,
                      const int* __restrict__ skill_idx,
                      const int* __restrict__ skill_mask,
                      const float* __restrict__ emb_s,
                      const float* __restrict__ batt,
                      float* __restrict__ out) {
    __shared__ __align__(16) float s_qs[5][100];
    __shared__ __align__(16) float s_hi[11][100];
    __shared__ float s_aq[5], s_ak[11], s_og[55], s_p[5];
    int root = blockIdx.x;
    int b = root / TMH, t = root % TMH;
    int tid = threadIdx.x;
    int w = tid >> 5, lane = tid & 31;
    int qn = question[b*TTOT + t + 1];
    const float4 z4 = make_float4(0.f,0.f,0.f,0.f);

    for (int row = w; row < 16; row += 4) {
        if (lane >= 25) continue;
        float4 v;
        if (row == 0) {
            v = ((const float4*)g_Qe)[(size_t)root*25 + lane];
        } else if (row < 5) {
            int j = row - 1;
            int sid = skill_idx[qn*4 + j];
            v = skill_mask[qn*4 + j] ? ((const float4*)emb_s)[sid*25 + lane] : z4;
        } else if (row == 5) {
            v = ((const float4*)g_lstm)[(size_t)root*25 + lane];
        } else {
            int idx = g_topk[root*RKK + row - 6];
            v = (idx > 0) ? ((const float4*)g_lstm)[(size_t)(b*TMH + idx)*25 + lane] : z4;
        }
        if (row < 5) ((float4*)&s_qs[row][0])[lane] = v;
        else         ((float4*)&s_hi[row-5][0])[lane] = v;
    }
    if (tid == 0) s_aq[0] = g_aqe[root];
    else if (tid < 5) {
        int j = tid - 1;
        int sid = skill_idx[qn*4 + j];
        s_aq[tid] = skill_mask[qn*4 + j] ? g_ast[sid] : g_aqzero;
    } else if (tid == 5) s_ak[0] = g_akl[root];
    else if (tid < 16) {
        int r = tid - 6;
        int idx = g_topk[root*RKK + r];
        s_ak[1 + r] = (idx > 0) ? g_akl[b*TMH + idx] : g_akzero;
    }
    __syncthreads();

    for (int d = w; d < 55; d += 4) {
        int q = d / 11, s = d % 11;
        const float* va = s_qs[q];
        const float* vb = s_hi[s];
        float p = 0.f;
#pragma unroll
        for (int u = 0; u < 4; u++) {
            int k = lane + u*32;
            if (k < 100) p += va[k]*vb[k];
        }
        p = warp_sum(p);
        if (lane == 0) s_og[d] = p;
    }
    __syncthreads();

    if (tid < 5) {
        int q = tid;
        float bb = batt[0];
        float tv[11];
        float m = -3.4e38f;
#pragma unroll
        for (int s = 0; s < 11; s++) {
            float tt = s_aq[q] + s_ak[s] + bb;
            if (s > 0 && g_topk[root*RKK + s - 1] < 0) tt = -1e9f;
            tv[s] = tt;
            if (tt > m) m = tt;
        }
        float se = 0.f, num = 0.f;
#pragma unroll
        for (int s = 0; s < 11; s++) {
            float e = __expf(tv[s] - m);
            se  += e;
            num += e * s_og[q*11 + s];
        }
        s_p[q] = __fdividef(num, se);
    }
    __syncthreads();
    if (tid == 0) {
        float p = s_p[0] + s_p[1] + s_p[2] + s_p[3] + s_p[4];
        out[b*TTOT + t + 1] = fast_sigm(p);
    }
    /* fused state output */
    if (t == TMH - 1 && tid < DIM)
        out[BBATCH*TTOT + b*DIM + tid] = g_lstm[(size_t)root*100 + tid];
}

/* ------------------------------------------------------------------ */
extern "C" void kernel_launch(void* const* d_in, const int* in_sizes, int n_in,
                              void* d_out, int out_size) {
    const int*   question  = (const int*)  d_in[0];
    const int*   response  = (const int*)  d_in[1];
    const int*   maskp     = (const int*)  d_in[2];
    const int*   q_nb      = (const int*)  d_in[3];
    const int*   s_nb      = (const int*)  d_in[4];
    const int*   skill_idx = (const int*)  d_in[5];
    const int*   skill_msk = (const int*)  d_in[6];
    const float* emb_q     = (const float*)d_in[7];
    const float* emb_s     = (const float*)d_in[8];
    const float* emb_r     = (const float*)d_in[9];
    const float* Wih       = (const float*)d_in[10];
    const float* lb        = (const float*)d_in[11];
    const float* aggW      = (const float*)d_in[12];
    const float* aggb      = (const float*)d_in[13];
    const float* aggLW     = (const float*)d_in[14];
    const float* aggLb     = (const float*)d_in[15];
    const float* Wq        = (const float*)d_in[16];
    const float* bq        = (const float*)d_in[17];
    const float* Wk        = (const float*)d_in[18];
    const float* bk        = (const float*)d_in[19];
    const float* watt      = (const float*)d_in[20];
    const float* batt      = (const float*)d_in[21];
    float* out = (float*)d_out;

    const int gb4  = (NROOT + 3)/4;
    const int gmE0 = (NROOT + 15)/16;     /* 398 */

    k_init<<<1, 128>>>(out, bq, bk, watt);
    k_prep<<<gb4, 128>>>(question, maskp, emb_q);

    /* dedupe tables (gathers fused into GEMM) */
    k_gemmg<<<(T2ROWS+15)/16, 128>>>(GM_T2X, OB_T2,  aggW + 2*10000, aggb + 200,
                                     T2ROWS, 0, q_nb, s_nb, emb_q, emb_s);
    k_gemmg<<<(NUMS+15)/16, 128>>>(GM_T1X, OB_T1A, aggW + 10000, aggb + 100,
                                     NUMS, 0, q_nb, s_nb, emb_q, emb_s);
    k_gemmg<<<(NUMS+15)/16, 128>>>(GM_T1B, OB_T1B, aggW + 10000, aggb + 100,
                                     NUMS, 0, q_nb, s_nb, emb_q, emb_s);

    /* e0 chain on active roots (in-place e0y -> e0y) */
    k_gemmg<<<gmE0, 128>>>(GM_E00, OB_E0Y, aggW, aggb, 0, 1, q_nb, s_nb, emb_q, emb_s);
    k_gemmg<<<gmE0, 128>>>(GM_E01, OB_E0Y, aggW, aggb, 0, 1, q_nb, s_nb, emb_q, emb_s);
    k_gemmg<<<gmE0, 128>>>(GM_E02, OB_E0Y, aggW, aggb, 0, 1, q_nb, s_nb, emb_q, emb_s);
    /* final agg + scatter into embq */
    k_gemmg<<<gmE0, 128>>>(GM_PLAIN, OB_EMBQ, aggLW, aggLb, 0, 1, q_nb, s_nb, emb_q, emb_s);

    /* fused LSTM */
    k_lstm<<<gmE0, 128>>>(response, emb_r, Wih, lb);

    /* scores + top-k */
    {
        dim3 g((TMH + 15)/16, 2, BBATCH);
        k_sgemm<<<g, 128>>>();
    }
    k_topk<<<gb4, 128>>>();

    /* attention scalar tables (merged) */
    k_gemvs3<<<398 + 398 + (NUMS+15)/16, 128>>>(Wq, bq, Wk, bk, watt, emb_s);

    k_att<<<NROOT, 128>>>(question, skill_idx, skill_msk, emb_s, batt, out);
    (void)in_sizes; (void)n_in; (void)out_size;
}

// round 8
// speedup vs baseline: 1.6054x; 1.6054x over previous
#include <cuda_runtime.h>
#include <math.h>
#include <stdint.h>

#define TMH    199
#define BBATCH 32
#define TTOT   200
#define DIM    100
#define NROOT  (BBATCH*TMH)   /* 6368 */
#define RKK    10
#define NUMS   1200
#define T2ROWS (NUMS*4)       /* 4800 */

/* ------------------------------------------------------------------ */
/* scratch                                                             */
/* ------------------------------------------------------------------ */
__device__ __align__(16) float g_plain[NROOT*DIM];
__device__ __align__(16) float g_Qe   [NROOT*DIM];
__device__ __align__(16) float g_embq [NROOT*DIM];
__device__ __align__(16) float g_t2   [T2ROWS*DIM];
__device__ __align__(16) float g_t1a  [NUMS*DIM];
__device__ __align__(16) float g_t1b  [NUMS*DIM];
__device__ __align__(16) float g_lstm [NROOT*DIM];
__device__ __align__(16) float g_sc   [NROOT*200];
__device__ __align__(16) float g_zero [DIM];      /* stays 0 */
__device__ float g_akl[NROOT];
__device__ float g_aqe[NROOT];
__device__ float g_ast[NUMS];
__device__ float g_akzero;
__device__ float g_aqzero;
__device__ int   g_topk[NROOT*RKK];
__device__ int   g_active[NROOT];
__device__ int   g_activeq[NROOT];
__device__ int   g_cnt;              /* reset at end of k_att */

#define GM_T2X   1
#define GM_T1X   2
#define GM_T1B   3

__device__ __forceinline__ float warp_sum(float v) {
#pragma unroll
    for (int o = 16; o; o >>= 1) v += __shfl_xor_sync(0xffffffffu, v, o);
    return v;
}
__device__ __forceinline__ float fast_tanh(float x) {
    return 1.f - __fdividef(2.f, __expf(2.f*x) + 1.f);
}
__device__ __forceinline__ float fast_sigm(float x) {
    return __fdividef(1.f, 1.f + __expf(-x));
}

/* vectorized load of a contiguous 100x100 W into Ws[c][j] (pad 101)   */
__device__ __forceinline__ void load_W100(float (*Ws)[101], const float* __restrict__ W, int tid) {
    const float4* W4 = (const float4*)W;
    for (int idx = tid; idx < 2500; idx += 128) {
        float4 v = W4[idx];
        int base = idx*4, c = base/100, j = base - c*100;
        Ws[c][j] = v.x; Ws[c][j+1] = v.y; Ws[c][j+2] = v.z; Ws[c][j+3] = v.w;
    }
}
/* Wih slab loader: row c has 200 floats, take [kt, kt+100) */
__device__ __forceinline__ void load_Wih(float (*Ws)[101], const float* __restrict__ Wih,
                                         int slab, int kt, int tid) {
    for (int idx = tid; idx < 2500; idx += 128) {
        int c = idx/25, j4 = idx - c*25;
        float4 v = *(const float4*)(Wih + (size_t)(slab + c)*200 + kt + j4*4);
        int j = j4*4;
        Ws[c][j] = v.x; Ws[c][j+1] = v.y; Ws[c][j+2] = v.z; Ws[c][j+3] = v.w;
    }
}

/* 16x100 @ 100x100^T mainloop, accumulate into acc                    */
__device__ __forceinline__ void mm16(const float (*Xs)[100], const float (*Ws)[101],
                                     int tx, int ty, float acc[4][4]) {
    bool w3ok = (tx < 4);
#pragma unroll 2
    for (int j4 = 0; j4 < 100; j4 += 4) {
        float xr[4][4];
#pragma unroll
        for (int i = 0; i < 4; i++)
            *(float4*)xr[i] = *(const float4*)&Xs[ty*4 + i][j4];
#pragma unroll
        for (int jj = 0; jj < 4; jj++) {
            int j = j4 + jj;
            float wv[4];
            wv[0] = Ws[tx][j];
            wv[1] = Ws[tx + 32][j];
            wv[2] = Ws[tx + 64][j];
            wv[3] = w3ok ? Ws[tx + 96][j] : 0.f;
#pragma unroll
            for (int i = 0; i < 4; i++)
#pragma unroll
                for (int c = 0; c < 4; c++) acc[i][c] += xr[i][jj]*wv[c];
        }
    }
}
__device__ __forceinline__ void zero_acc(float acc[4][4]) {
#pragma unroll
    for (int i = 0; i < 4; i++)
#pragma unroll
        for (int c = 0; c < 4; c++) acc[i][c] = 0.f;
}

/* ------------------------------------------------------------------ */
/* prep (+ init folded into block 0)                                   */
/* ------------------------------------------------------------------ */
__global__ void k_prep(const int* __restrict__ question,
                       const int* __restrict__ mask,
                       const float* __restrict__ emb_q,
                       const float* __restrict__ bq,
                       const float* __restrict__ bk,
                       const float* __restrict__ watt,
                       float* __restrict__ out) {
    int tid = threadIdx.x, w = tid >> 5, lane = tid & 31;
    int root = blockIdx.x*4 + w;
    if (root < NROOT) {
        int b = root / TMH, t = root % TMH;
        int qh = question[b*TTOT + t];
        int qn = question[b*TTOT + t + 1];
        if (lane < 25) {
            const float4* eq = (const float4*)emb_q;
            float4 vh = eq[qh*25 + lane];
            float4 vn = eq[qn*25 + lane];
            ((float4*)g_plain)[root*25 + lane] = vh;
            ((float4*)g_embq )[root*25 + lane] = vh;
            ((float4*)g_Qe   )[root*25 + lane] = vn;
        }
        if (lane == 0 && mask[b*TTOT + t] == 1) {
            int pos = atomicAdd(&g_cnt, 1);
            g_active[pos]  = root;
            g_activeq[pos] = qh;
        }
    }
    if (blockIdx.x == 0) {
        if (w == 0) {
            float s = 0.f;
            for (int c = lane; c < DIM; c += 32) s += fast_tanh(bq[c]) * watt[DIM + c];
            s = warp_sum(s);
            if (lane == 0) g_akzero = s;
        } else if (w == 1) {
            float s = 0.f;
            for (int c = lane; c < DIM; c += 32) s += fast_tanh(bk[c]) * watt[c];
            s = warp_sum(s);
            if (lane == 0) g_aqzero = s;
        } else if (w == 2) {
            out[lane*TTOT] = 0.5f;
        }
    }
}

/* ------------------------------------------------------------------ */
/* job helpers for the fat kernels                                     */
/* ------------------------------------------------------------------ */
__device__ void do_ggather(int gmode, float* __restrict__ Y,
                           const float* __restrict__ W, const float* __restrict__ bias,
                           int rows, int bi,
                           const int* __restrict__ qnb, const int* __restrict__ snb,
                           const float* __restrict__ emb_q, const float* __restrict__ emb_s,
                           float (*Xs)[100], float (*Ws)[101],
                           const float* (*s_p0), const float* (*s_pn)[4], int tid) {
    int r0 = bi*16;
    if (r0 >= rows) return;
    int tx = tid & 31, ty = tid >> 5;
    if (tid < 16) {
        int gr = r0 + tid;
        const float *p0 = g_zero, *a0 = g_zero, *a1 = g_zero, *a2 = g_zero, *a3 = g_zero;
        if (gr < rows) {
            if (gmode == GM_T2X) {
                int n2 = snb[gr];
                p0 = emb_q + (size_t)n2*DIM;
                a0 = emb_s + (size_t)qnb[n2*4 + 0]*DIM;
                a1 = emb_s + (size_t)qnb[n2*4 + 1]*DIM;
                a2 = emb_s + (size_t)qnb[n2*4 + 2]*DIM;
                a3 = emb_s + (size_t)qnb[n2*4 + 3]*DIM;
            } else if (gmode == GM_T1X) {
                p0 = emb_s + (size_t)gr*DIM;
                a0 = emb_q + (size_t)snb[gr*4 + 0]*DIM;
                a1 = emb_q + (size_t)snb[gr*4 + 1]*DIM;
                a2 = emb_q + (size_t)snb[gr*4 + 2]*DIM;
                a3 = emb_q + (size_t)snb[gr*4 + 3]*DIM;
            } else { /* GM_T1B */
                p0 = g_t1a + (size_t)gr*DIM;
                a0 = g_t2 + (size_t)(gr*4 + 0)*DIM;
                a1 = g_t2 + (size_t)(gr*4 + 1)*DIM;
                a2 = g_t2 + (size_t)(gr*4 + 2)*DIM;
                a3 = g_t2 + (size_t)(gr*4 + 3)*DIM;
            }
        }
        s_p0[tid] = p0;
        s_pn[tid][0] = a0; s_pn[tid][1] = a1; s_pn[tid][2] = a2; s_pn[tid][3] = a3;
    }
    load_W100(Ws, W, tid);
    __syncthreads();
    for (int idx = tid; idx < 400; idx += 128) {
        int r = idx/25, j = idx - r*25;
        float4 v  = ((const float4*)s_p0[r])[j];
        float4 n0 = ((const float4*)s_pn[r][0])[j];
        float4 n1 = ((const float4*)s_pn[r][1])[j];
        float4 n2 = ((const float4*)s_pn[r][2])[j];
        float4 n3 = ((const float4*)s_pn[r][3])[j];
        v.x += 0.25f*(n0.x + n1.x + n2.x + n3.x);
        v.y += 0.25f*(n0.y + n1.y + n2.y + n3.y);
        v.z += 0.25f*(n0.z + n1.z + n2.z + n3.z);
        v.w += 0.25f*(n0.w + n1.w + n2.w + n3.w);
        ((float4*)&Xs[r][0])[j] = v;
    }
    __syncthreads();
    float acc[4][4];
    zero_acc(acc);
    mm16(Xs, Ws, tx, ty, acc);
#pragma unroll
    for (int i = 0; i < 4; i++) {
        int r = r0 + ty*4 + i;
        if (r >= rows) continue;
#pragma unroll
        for (int cc = 0; cc < 4; cc++) {
            int c = tx + cc*32;
            if (c < 100) Y[(size_t)r*100 + c] = fast_tanh(acc[i][cc] + bias[c]);
        }
    }
}

__device__ void do_gemv(const float* __restrict__ X,
                        const float* __restrict__ W, const float* __restrict__ bias,
                        const float* __restrict__ wvec, float* __restrict__ Out,
                        int rows, int bi,
                        float (*Xs)[100], float (*Ws)[101], int tid) {
    int r0 = bi*16;
    if (r0 >= rows) return;
    int tx = tid & 31, ty = tid >> 5;
    const float4* X4 = (const float4*)X;
    for (int idx = tid; idx < 400; idx += 128) {
        int r = idx/25, j = idx - r*25;
        int gr = r0 + r;
        float4 v = make_float4(0.f,0.f,0.f,0.f);
        if (gr < rows) v = X4[(size_t)gr*25 + j];
        ((float4*)&Xs[r][0])[j] = v;
    }
    load_W100(Ws, W, tid);
    __syncthreads();
    float acc[4][4];
    zero_acc(acc);
    mm16(Xs, Ws, tx, ty, acc);
    float bv[4], wvv[4];
#pragma unroll
    for (int cc = 0; cc < 4; cc++) {
        int c = tx + cc*32;
        bv[cc]  = (c < 100) ? bias[c] : 0.f;
        wvv[cc] = (c < 100) ? wvec[c] : 0.f;
    }
#pragma unroll
    for (int i = 0; i < 4; i++) {
        float s = 0.f;
#pragma unroll
        for (int cc = 0; cc < 4; cc++) {
            int c = tx + cc*32;
            if (c < 100) s += fast_tanh(acc[i][cc] + bv[cc]) * wvv[cc];
        }
        s = warp_sum(s);
        int r = r0 + ty*4 + i;
        if (tx == 0 && r < rows) Out[r] = s;
    }
}

__device__ void do_sgemm(int u, float (*Xs)[100], float (*Ps)[101], int tid) {
    int b = u / 26, rr = u - b*26;
    int t0 = (rr >> 1)*16, s0 = (rr & 1)*100;
    if (s0 > t0 + 14) return;
    int tx = tid & 31, ty = tid >> 5;
    const float4* Q4 = (const float4*)g_Qe;
    const float4* P4 = (const float4*)g_plain;
    for (int idx = tid; idx < 400; idx += 128) {
        int r = idx/25, j = idx - r*25;
        int t = t0 + r;
        float4 v = make_float4(0.f,0.f,0.f,0.f);
        if (t < TMH) v = Q4[(size_t)(b*TMH + t)*25 + j];
        ((float4*)&Xs[r][0])[j] = v;
    }
    for (int idx = tid; idx < 2500; idx += 128) {
        int s = idx/25, j4 = idx - s*25;
        int gs = s0 + s;
        float4 v = make_float4(0.f,0.f,0.f,0.f);
        if (gs < TMH) v = P4[(size_t)(b*TMH + gs)*25 + j4];
        int j = j4*4;
        Ps[s][j] = v.x; Ps[s][j+1] = v.y; Ps[s][j+2] = v.z; Ps[s][j+3] = v.w;
    }
    __syncthreads();
    float acc[4][4];
    zero_acc(acc);
    mm16(Xs, Ps, tx, ty, acc);
#pragma unroll
    for (int i = 0; i < 4; i++) {
        int t = t0 + ty*4 + i;
        if (t >= TMH) continue;
#pragma unroll
        for (int cc = 0; cc < 4; cc++) {
            int c = tx + cc*32;
            int s = s0 + c;
            if (c < 100 && s < TMH)
                g_sc[(size_t)(b*TMH + t)*200 + s] = acc[i][cc];
        }
    }
}

__device__ void do_topk(int root) {
    int lane = threadIdx.x & 31;
    if (root >= NROOT) return;
    int t = root % TMH;
    float rv[7];
#pragma unroll
    for (int u = 0; u < 7; u++) {
        int s = lane + u*32;
        rv[u] = (s < t) ? g_sc[(size_t)root*200 + s] : -3.4e38f;
    }
#pragma unroll
    for (int r = 0; r < RKK; r++) {
        float bv = -3.4e38f;
        int   bi = 0x7fffffff;
#pragma unroll
        for (int u = 0; u < 7; u++) {
            int s = lane + u*32;
            if (s < t && rv[u] > bv) { bv = rv[u]; bi = s; }
        }
#pragma unroll
        for (int o = 16; o; o >>= 1) {
            float ov = __shfl_xor_sync(0xffffffffu, bv, o);
            int   oi = __shfl_xor_sync(0xffffffffu, bi, o);
            if (ov > bv || (ov == bv && oi < bi)) { bv = ov; bi = oi; }
        }
        if (lane == 0)
            g_topk[root*RKK + r] = (bv > -1e29f) ? bi : -1;
        if (bi != 0x7fffffff && (bi & 31) == lane)
            rv[bi >> 5] = -3.4e38f;
    }
}

/* ------------------------------------------------------------------ */
/* stage2: T2(300) + T1A(75) + aqe(398) + ast(75) + sgemm(832)         */
/* ------------------------------------------------------------------ */
__global__ void __launch_bounds__(128) k_stage2(
                         const int* __restrict__ qnb, const int* __restrict__ snb,
                         const float* __restrict__ emb_q, const float* __restrict__ emb_s,
                         const float* __restrict__ aggW, const float* __restrict__ aggb,
                         const float* __restrict__ Wk, const float* __restrict__ bk,
                         const float* __restrict__ watt) {
    __shared__ __align__(16) float Xs[16][100];
    __shared__ float Ws[100][101];
    __shared__ const float* s_p0[16];
    __shared__ const float* s_pn[16][4];
    int blk = blockIdx.x, tid = threadIdx.x;
    if (blk < 300)
        do_ggather(GM_T2X, g_t2, aggW + 20000, aggb + 200, T2ROWS, blk,
                   qnb, snb, emb_q, emb_s, Xs, Ws, s_p0, s_pn, tid);
    else if (blk < 375)
        do_ggather(GM_T1X, g_t1a, aggW + 10000, aggb + 100, NUMS, blk - 300,
                   qnb, snb, emb_q, emb_s, Xs, Ws, s_p0, s_pn, tid);
    else if (blk < 773)
        do_gemv(g_Qe, Wk, bk, watt, g_aqe, NROOT, blk - 375, Xs, Ws, tid);
    else if (blk < 848)
        do_gemv(emb_s, Wk, bk, watt, g_ast, NUMS, blk - 773, Xs, Ws, tid);
    else
        do_sgemm(blk - 848, Xs, Ws, tid);
}

/* ------------------------------------------------------------------ */
/* stage3: T1B(75) + topk(1592)                                        */
/* ------------------------------------------------------------------ */
__global__ void __launch_bounds__(128) k_stage3(
                         const int* __restrict__ qnb, const int* __restrict__ snb,
                         const float* __restrict__ emb_q, const float* __restrict__ emb_s,
                         const float* __restrict__ aggW, const float* __restrict__ aggb) {
    __shared__ __align__(16) float Xs[16][100];
    __shared__ float Ws[100][101];
    __shared__ const float* s_p0[16];
    __shared__ const float* s_pn[16][4];
    int blk = blockIdx.x, tid = threadIdx.x;
    if (blk < 75)
        do_ggather(GM_T1B, g_t1b, aggW + 10000, aggb + 100, NUMS, blk,
                   qnb, snb, emb_q, emb_s, Xs, Ws, s_p0, s_pn, tid);
    else
        do_topk((blk - 75)*4 + (tid >> 5));
}

/* ------------------------------------------------------------------ */
/* fused e0 chain: E00 -> E01 -> E02 -> aggL, scatter into embq        */
/* ------------------------------------------------------------------ */
__global__ void __launch_bounds__(128) k_e0chain(
                          const int* __restrict__ qnb,
                          const float* __restrict__ emb_q, const float* __restrict__ emb_s,
                          const float* __restrict__ aggW, const float* __restrict__ aggb,
                          const float* __restrict__ aggLW, const float* __restrict__ aggLb) {
    __shared__ __align__(16) float Xs[16][100];
    __shared__ float Ws[100][101];
    __shared__ int s_nbr[16][4];
    __shared__ int s_q[16];
    int rows = g_cnt;
    int r0 = blockIdx.x*16;
    if (r0 >= rows) return;
    int tid = threadIdx.x, tx = tid & 31, ty = tid >> 5;

    if (tid < 16) {
        int gr = r0 + tid;
        int q = (gr < rows) ? g_activeq[gr] : -1;
        s_q[tid] = q;
#pragma unroll
        for (int k = 0; k < 4; k++)
            s_nbr[tid][k] = (q >= 0) ? qnb[q*4 + k] : 0;
    }
    load_W100(Ws, aggW, tid);
    __syncthreads();

    /* E00 gather */
    {
        const float4* eq = (const float4*)emb_q;
        const float4* es = (const float4*)emb_s;
        for (int idx = tid; idx < 400; idx += 128) {
            int r = idx/25, j = idx - r*25;
            float4 v = make_float4(0.f,0.f,0.f,0.f);
            int q = s_q[r];
            if (q >= 0) {
                v = eq[(size_t)q*25 + j];
#pragma unroll
                for (int k = 0; k < 4; k++) {
                    float4 n = es[(size_t)s_nbr[r][k]*25 + j];
                    v.x += 0.25f*n.x; v.y += 0.25f*n.y; v.z += 0.25f*n.z; v.w += 0.25f*n.w;
                }
            }
            ((float4*)&Xs[r][0])[j] = v;
        }
    }
    __syncthreads();

    float b0[4], bL[4];
#pragma unroll
    for (int cc = 0; cc < 4; cc++) {
        int c = tx + cc*32;
        b0[cc] = (c < 100) ? aggb[c]  : 0.f;
        bL[cc] = (c < 100) ? aggLb[c] : 0.f;
    }

    float acc[4][4];
    /* three passes with aggW0: E00 out, E01 out, E02 out */
#pragma unroll 1
    for (int pass = 0; pass < 3; pass++) {
        zero_acc(acc);
        mm16(Xs, Ws, tx, ty, acc);
        __syncthreads();                    /* everyone done reading Xs */
#pragma unroll
        for (int i = 0; i < 4; i++)
#pragma unroll
            for (int cc = 0; cc < 4; cc++) {
                int c = tx + cc*32;
                if (c < 100) Xs[ty*4 + i][c] = fast_tanh(acc[i][cc] + b0[cc]);
            }
        __syncthreads();
        if (pass < 2) {
            const float4* tab = (pass == 0) ? (const float4*)g_t1a : (const float4*)g_t1b;
            for (int idx = tid; idx < 400; idx += 128) {
                int r = idx/25, j = idx - r*25;
                if (s_q[r] < 0) continue;
                float4 v = ((float4*)&Xs[r][0])[j];
#pragma unroll
                for (int k = 0; k < 4; k++) {
                    float4 n = tab[(size_t)s_nbr[r][k]*25 + j];
                    v.x += 0.25f*n.x; v.y += 0.25f*n.y; v.z += 0.25f*n.z; v.w += 0.25f*n.w;
                }
                ((float4*)&Xs[r][0])[j] = v;
            }
            __syncthreads();
        }
    }
    /* final aggL GEMM, scatter into g_embq */
    load_W100(Ws, aggLW, tid);
    __syncthreads();
    zero_acc(acc);
    mm16(Xs, Ws, tx, ty, acc);
#pragma unroll
    for (int i = 0; i < 4; i++) {
        int r = r0 + ty*4 + i;
        if (r >= rows) continue;
        size_t root = (size_t)g_active[r];
#pragma unroll
        for (int cc = 0; cc < 4; cc++) {
            int c = tx + cc*32;
            if (c < 100) g_embq[root*100 + c] = fast_tanh(acc[i][cc] + bL[cc]);
        }
    }
}

/* ------------------------------------------------------------------ */
/* fused LSTM + akl GEMV                                               */
/* ------------------------------------------------------------------ */
__global__ void __launch_bounds__(128) k_lstm(
                       const int* __restrict__ response,
                       const float* __restrict__ emb_r,
                       const float* __restrict__ Wih,
                       const float* __restrict__ lb,
                       const float* __restrict__ Wq,
                       const float* __restrict__ bq,
                       const float* __restrict__ watt) {
    __shared__ __align__(16) float Xs[16][100];
    __shared__ float Ws[100][101];
    int r0 = blockIdx.x * 16;
    int tid = threadIdx.x, tx = tid & 31, ty = tid >> 5;
    float acc3[3][4][4];
#pragma unroll
    for (int s = 0; s < 3; s++) zero_acc(acc3[s]);
    const int slab_row[3] = {0, 200, 300};   /* i, g, o */

    for (int kt = 0; kt < 200; kt += 100) {
        __syncthreads();
        for (int idx = tid; idx < 400; idx += 128) {
            int r = idx/25, j = idx - r*25;
            int gr = r0 + r;
            float4 v;
            if (kt == 0) v = ((const float4*)g_embq)[(size_t)gr*25 + j];
            else {
                int b = gr / TMH, t = gr % TMH;
                v = ((const float4*)emb_r)[(size_t)response[b*TTOT + t]*25 + j];
            }
            ((float4*)&Xs[r][0])[j] = v;
        }
#pragma unroll
        for (int s = 0; s < 3; s++) {
            __syncthreads();
            load_Wih(Ws, Wih, slab_row[s], kt, tid);
            __syncthreads();
            mm16(Xs, Ws, tx, ty, acc3[s]);
        }
    }
    /* lstm combine -> g_lstm + Xs */
    __syncthreads();
#pragma unroll
    for (int i = 0; i < 4; i++) {
        int r = r0 + ty*4 + i;
#pragma unroll
        for (int cc = 0; cc < 4; cc++) {
            int c = tx + cc*32;
            if (c >= 100) continue;
            float gi = acc3[0][i][cc] + lb[c];
            float gg = acc3[1][i][cc] + lb[200 + c];
            float go = acc3[2][i][cc] + lb[300 + c];
            float v = fast_sigm(go) * fast_tanh(fast_sigm(gi) * fast_tanh(gg));
            g_lstm[(size_t)r*100 + c] = v;
            Xs[ty*4 + i][c] = v;
        }
    }
    __syncthreads();
    /* akl = tanh(lstm @ Wq^T + bq) . watt[100:] */
    load_W100(Ws, Wq, tid);
    __syncthreads();
    float acc[4][4];
    zero_acc(acc);
    mm16(Xs, Ws, tx, ty, acc);
    float bv[4], wvv[4];
#pragma unroll
    for (int cc = 0; cc < 4; cc++) {
        int c = tx + cc*32;
        bv[cc]  = (c < 100) ? bq[c] : 0.f;
        wvv[cc] = (c < 100) ? watt[DIM + c] : 0.f;
    }
#pragma unroll
    for (int i = 0; i < 4; i++) {
        float s = 0.f;
#pragma unroll
        for (int cc = 0; cc < 4; cc++) {
            int c = tx + cc*32;
            if (c < 100) s += fast_tanh(acc[i][cc] + bv[cc]) * wvv[cc];
        }
        s = warp_sum(s);
        if (tx == 0) g_akl[r0 + ty*4 + i] = s;
    }
}

/* ------------------------------------------------------------------ */
/* final attention (+ state rows + g_cnt reset)                        */
/* ------------------------------------------------------------------ */
__global__ void __launch_bounds__(128) k_att(
                      const int* __restrict__ question,
                      const int* __restrict__ skill_idx,
                      const int* __restrict__ skill_mask,
                      const float* __restrict__ emb_s,
                      const float* __restrict__ batt,
                      float* __restrict__ out) {
    __shared__ __align__(16) float s_qs[5][100];
    __shared__ __align__(16) float s_hi[11][100];
    __shared__ float s_aq[5], s_ak[11], s_og[55], s_p[5];
    int root = blockIdx.x;
    int b = root / TMH, t = root % TMH;
    int tid = threadIdx.x;
    int w = tid >> 5, lane = tid & 31;
    int qn = question[b*TTOT + t + 1];
    const float4 z4 = make_float4(0.f,0.f,0.f,0.f);

    for (int row = w; row < 16; row += 4) {
        if (lane >= 25) continue;
        float4 v;
        if (row == 0) {
            v = ((const float4*)g_Qe)[(size_t)root*25 + lane];
        } else if (row < 5) {
            int j = row - 1;
            int sid = skill_idx[qn*4 + j];
            v = skill_mask[qn*4 + j] ? ((const float4*)emb_s)[sid*25 + lane] : z4;
        } else if (row == 5) {
            v = ((const float4*)g_lstm)[(size_t)root*25 + lane];
        } else {
            int idx = g_topk[root*RKK + row - 6];
            v = (idx > 0) ? ((const float4*)g_lstm)[(size_t)(b*TMH + idx)*25 + lane] : z4;
        }
        if (row < 5) ((float4*)&s_qs[row][0])[lane] = v;
        else         ((float4*)&s_hi[row-5][0])[lane] = v;
    }
    if (tid == 0) s_aq[0] = g_aqe[root];
    else if (tid < 5) {
        int j = tid - 1;
        int sid = skill_idx[qn*4 + j];
        s_aq[tid] = skill_mask[qn*4 + j] ? g_ast[sid] : g_aqzero;
    } else if (tid == 5) s_ak[0] = g_akl[root];
    else if (tid < 16) {
        int r = tid - 6;
        int idx = g_topk[root*RKK + r];
        s_ak[1 + r] = (idx > 0) ? g_akl[b*TMH + idx] : g_akzero;
    }
    __syncthreads();

    for (int d = w; d < 55; d += 4) {
        int q = d / 11, s = d % 11;
        const float* va = s_qs[q];
        const float* vb = s_hi[s];
        float p = 0.f;
#pragma unroll
        for (int u = 0; u < 4; u++) {
            int k = lane + u*32;
            if (k < 100) p += va[k]*vb[k];
        }
        p = warp_sum(p);
        if (lane == 0) s_og[d] = p;
    }
    __syncthreads();

    if (tid < 5) {
        int q = tid;
        float bb = batt[0];
        float tv[11];
        float m = -3.4e38f;
#pragma unroll
        for (int s = 0; s < 11; s++) {
            float tt = s_aq[q] + s_ak[s] + bb;
            if (s > 0 && g_topk[root*RKK + s - 1] < 0) tt = -1e9f;
            tv[s] = tt;
            if (tt > m) m = tt;
        }
        float se = 0.f, num = 0.f;
#pragma unroll
        for (int s = 0; s < 11; s++) {
            float e = __expf(tv[s] - m);
            se  += e;
            num += e * s_og[q*11 + s];
        }
        s_p[q] = __fdividef(num, se);
    }
    __syncthreads();
    if (tid == 0) {
        float p = s_p[0] + s_p[1] + s_p[2] + s_p[3] + s_p[4];
        out[b*TTOT + t + 1] = fast_sigm(p);
        if (root == 0) g_cnt = 0;           /* reset for next replay */
    }
    if (t == TMH - 1 && tid < DIM)
        out[BBATCH*TTOT + b*DIM + tid] = g_lstm[(size_t)root*100 + tid];
}

/* ------------------------------------------------------------------ */
extern "C" void kernel_launch(void* const* d_in, const int* in_sizes, int n_in,
                              void* d_out, int out_size) {
    const int*   question  = (const int*)  d_in[0];
    const int*   response  = (const int*)  d_in[1];
    const int*   maskp     = (const int*)  d_in[2];
    const int*   q_nb      = (const int*)  d_in[3];
    const int*   s_nb      = (const int*)  d_in[4];
    const int*   skill_idx = (const int*)  d_in[5];
    const int*   skill_msk = (const int*)  d_in[6];
    const float* emb_q     = (const float*)d_in[7];
    const float* emb_s     = (const float*)d_in[8];
    const float* emb_r     = (const float*)d_in[9];
    const float* Wih       = (const float*)d_in[10];
    const float* lb        = (const float*)d_in[11];
    const float* aggW      = (const float*)d_in[12];
    const float* aggb      = (const float*)d_in[13];
    const float* aggLW     = (const float*)d_in[14];
    const float* aggLb     = (const float*)d_in[15];
    const float* Wq        = (const float*)d_in[16];
    const float* bq        = (const float*)d_in[17];
    const float* Wk        = (const float*)d_in[18];
    const float* bk        = (const float*)d_in[19];
    const float* watt      = (const float*)d_in[20];
    const float* batt      = (const float*)d_in[21];
    float* out = (float*)d_out;

    k_prep<<<(NROOT + 3)/4, 128>>>(question, maskp, emb_q, bq, bk, watt, out);
    k_stage2<<<1680, 128>>>(q_nb, s_nb, emb_q, emb_s, aggW, aggb, Wk, bk, watt);
    k_stage3<<<75 + (NROOT + 3)/4, 128>>>(q_nb, s_nb, emb_q, emb_s, aggW, aggb);
    k_e0chain<<<(NROOT + 15)/16, 128>>>(q_nb, emb_q, emb_s, aggW, aggb, aggLW, aggLb);
    k_lstm<<<(NROOT + 15)/16, 128>>>(response, emb_r, Wih, lb, Wq, bq, watt);
    k_att<<<NROOT, 128>>>(question, skill_idx, skill_msk, emb_s, batt, out);
    (void)in_sizes; (void)n_in; (void)out_size;
}